// round 1
// baseline (speedup 1.0000x reference)
#include <cuda_runtime.h>
#include <cstdint>

#define KS    9
#define PADV  4
#define CIN   32
#define COUT  32
#define HH    192
#define WW    192
#define NB    16

#define TILE  64
#define SROW  72          // TILE + 2*PADV + (KS-1-2*PADV) = 64 + 8 halo

typedef unsigned long long u64;

// Precomputed Gaussian kernels, duplicated as {w, w} pairs for f32x2 broadcast.
__device__ float2 g_w2[COUT * CIN * 81];

// ---------------------------------------------------------------------------
// Phase 1: build normalized anisotropic Gaussian kernels from (sx, sy, theta)
// ---------------------------------------------------------------------------
__global__ void gk_compute(const float* __restrict__ wp) {
    int co = blockIdx.x;
    int ci = threadIdx.x;
    const float* p = wp + (co * CIN + ci) * 3;
    float sx = p[0], sy = p[1], th = p[2];
    float rad = th * 0.017453292519943295f;   // th / 180 * pi  (matches reference)
    float c = cosf(rad), s = sinf(rad);
    float sx2 = sx * sx, sy2 = sy * sy;
    float a = c * c * sx2 + s * s * sy2;
    float b = c * s * (sx2 - sy2);
    float d = s * s * sx2 + c * c * sy2;
    float det = a * d - b * b;
    float ia = d / det, ib = -b / det, idd = a / det;

    float ker[81];
    float sum = 0.f;
    #pragma unroll
    for (int ky = 0; ky < 9; ky++) {
        float yy = (float)(ky - 4);
        #pragma unroll
        for (int kx = 0; kx < 9; kx++) {
            float xx = (float)(kx - 4);
            float q = ia * xx * xx + 2.0f * ib * xx * yy + idd * yy * yy;
            float v = expf(-0.5f * q);
            ker[ky * 9 + kx] = v;
            sum += v;
        }
    }
    float inv = 1.0f / sum;
    float2* dst = &g_w2[(co * CIN + ci) * 81];
    #pragma unroll
    for (int t = 0; t < 81; t++) {
        float w = ker[t] * inv;
        dst[t] = make_float2(w, w);
    }
}

// ---------------------------------------------------------------------------
// Packed f32x2 helpers (FFMA2: 2x the fp32 FMA throughput of 3-reg FFMA)
// ---------------------------------------------------------------------------
__device__ __forceinline__ u64 pk2(float lo, float hi) {
    u64 r;
    asm("mov.b64 %0, {%1, %2};" : "=l"(r) : "f"(lo), "f"(hi));
    return r;
}
__device__ __forceinline__ void fma2(u64& d, u64 a, u64 b) {
    asm("fma.rn.f32x2 %0, %1, %2, %0;" : "+l"(d) : "l"(a), "l"(b));
}

// ---------------------------------------------------------------------------
// Phase 2: direct conv. Block = 256 threads, one (n, co), 64x64 output tile.
// Each thread: 4 wide x 4 tall outputs as 8 packed f32x2 accumulators.
// ---------------------------------------------------------------------------
__global__ __launch_bounds__(256, 2)
void conv_kernel(const float* __restrict__ x,
                 const float* __restrict__ bias,
                 float* __restrict__ out) {
    __shared__ __align__(16) float tile[SROW * SROW];
    __shared__ __align__(8)  float2 wsh[CIN * 81];

    const int tid = threadIdx.y * 16 + threadIdx.x;
    const int x0 = blockIdx.x * TILE;
    const int y0 = blockIdx.y * TILE;
    const int n  = blockIdx.z >> 5;
    const int co = blockIdx.z & 31;

    // All 32 input-channel kernels for this output channel -> smem (pre-packed pairs)
    for (int i = tid; i < CIN * 81; i += 256) wsh[i] = g_w2[co * CIN * 81 + i];

    const int ox0 = threadIdx.x * 4;   // output x within tile
    const int oy0 = threadIdx.y * 4;   // output y within tile

    u64 acc[4][2] = {};                // {0.f, 0.f} pairs

    const float* xn = x + (size_t)n * CIN * HH * WW;

    for (int ci = 0; ci < CIN; ci++) {
        __syncthreads();               // protect tile reuse + (first iter) weight load
        const float* xc = xn + (size_t)ci * HH * WW;
        // Stage 72x72 zero-padded input tile
        for (int i = tid; i < SROW * SROW; i += 256) {
            int r  = i / SROW;
            int cc = i - r * SROW;
            int gy = y0 - PADV + r;
            int gx = x0 - PADV + cc;
            float v = 0.f;
            if ((unsigned)gy < HH && (unsigned)gx < WW) v = xc[gy * WW + gx];
            tile[i] = v;
        }
        __syncthreads();

        const u64* w2 = (const u64*)(wsh + ci * 81);

        #pragma unroll
        for (int r = 0; r < 12; r++) {         // input rows oy0 .. oy0+11
            float f[12];
            const float* trow = &tile[(oy0 + r) * SROW + ox0];
            *(float4*)(f + 0) = *(const float4*)(trow + 0);
            *(float4*)(f + 4) = *(const float4*)(trow + 4);
            *(float4*)(f + 8) = *(const float4*)(trow + 8);
            #pragma unroll
            for (int kx = 0; kx < 9; kx++) {
                u64 p0 = pk2(f[kx],     f[kx + 1]);   // outputs ox0+0, ox0+1
                u64 p1 = pk2(f[kx + 2], f[kx + 3]);   // outputs ox0+2, ox0+3
                #pragma unroll
                for (int oy = 0; oy < 4; oy++) {
                    const int ky = r - oy;            // constant after unroll
                    if (ky >= 0 && ky < 9) {
                        u64 wv = w2[ky * 9 + kx];     // 64-bit smem broadcast
                        fma2(acc[oy][0], p0, wv);
                        fma2(acc[oy][1], p1, wv);
                    }
                }
            }
        }
    }

    const float bv = bias[co];
    float* op = out + (((size_t)(n * COUT + co) * HH + (y0 + oy0)) * WW + x0 + ox0);
    #pragma unroll
    for (int oy = 0; oy < 4; oy++) {
        float o0, o1, o2, o3;
        asm("mov.b64 {%0, %1}, %2;" : "=f"(o0), "=f"(o1) : "l"(acc[oy][0]));
        asm("mov.b64 {%0, %1}, %2;" : "=f"(o2), "=f"(o3) : "l"(acc[oy][1]));
        float4 ov = make_float4(o0 + bv, o1 + bv, o2 + bv, o3 + bv);
        *(float4*)(op + (size_t)oy * WW) = ov;
    }
}

// ---------------------------------------------------------------------------
extern "C" void kernel_launch(void* const* d_in, const int* in_sizes, int n_in,
                              void* d_out, int out_size) {
    const float* x    = (const float*)d_in[0];   // [16, 32, 192, 192]
    const float* wp   = (const float*)d_in[1];   // [32, 32, 3]
    const float* bias = (const float*)d_in[2];   // [32]
    float* out = (float*)d_out;                  // [16, 32, 192, 192]

    gk_compute<<<COUT, CIN>>>(wp);

    dim3 grid(WW / TILE, HH / TILE, NB * COUT);  // (3, 3, 512)
    dim3 blk(16, 16);
    conv_kernel<<<grid, blk>>>(x, bias, out);
}

// round 3
// speedup vs baseline: 1.1602x; 1.1602x over previous
#include <cuda_runtime.h>
#include <cstdint>

#define KS    9
#define PADV  4
#define CIN   32
#define COUT  32
#define HH    192
#define WW    192
#define NB    16

#define TILE  64
#define SROW  72                 // 64 + 8 halo
#define TILE_ELEMS (SROW * SROW) // 5184
#define WROW  10                 // 9 taps padded to 10 u64 (16B alignment)

typedef unsigned long long u64;

// Precomputed Gaussian kernels, duplicated as {w,w} u64 pairs, rows padded to 10.
__device__ u64 g_w2p[COUT * CIN * 9 * WROW];

// ---------------------------------------------------------------------------
// Phase 1: build normalized anisotropic Gaussian kernels from (sx, sy, theta)
// ---------------------------------------------------------------------------
__global__ void gk_compute(const float* __restrict__ wp) {
    int co = blockIdx.x;
    int ci = threadIdx.x;
    const float* p = wp + (co * CIN + ci) * 3;
    float sx = p[0], sy = p[1], th = p[2];
    float rad = th * 0.017453292519943295f;   // th / 180 * pi
    float c = cosf(rad), s = sinf(rad);
    float sx2 = sx * sx, sy2 = sy * sy;
    float a = c * c * sx2 + s * s * sy2;
    float b = c * s * (sx2 - sy2);
    float d = s * s * sx2 + c * c * sy2;
    float det = a * d - b * b;
    float ia = d / det, ib = -b / det, idd = a / det;

    float ker[81];
    float sum = 0.f;
    #pragma unroll
    for (int ky = 0; ky < 9; ky++) {
        float yy = (float)(ky - 4);
        #pragma unroll
        for (int kx = 0; kx < 9; kx++) {
            float xx = (float)(kx - 4);
            float q = ia * xx * xx + 2.0f * ib * xx * yy + idd * yy * yy;
            float v = expf(-0.5f * q);
            ker[ky * 9 + kx] = v;
            sum += v;
        }
    }
    float inv = 1.0f / sum;
    u64* dst = &g_w2p[(co * CIN + ci) * 9 * WROW];
    #pragma unroll
    for (int ky = 0; ky < 9; ky++) {
        #pragma unroll
        for (int kx = 0; kx < 9; kx++) {
            float w = ker[ky * 9 + kx] * inv;
            union { float f[2]; u64 q; } u;
            u.f[0] = w; u.f[1] = w;
            dst[ky * WROW + kx] = u.q;
        }
        dst[ky * WROW + 9] = 0ull;   // pad
    }
}

// ---------------------------------------------------------------------------
// f32x2 helpers
// ---------------------------------------------------------------------------
__device__ __forceinline__ u64 pk2(float lo, float hi) {
    u64 r;
    asm("mov.b64 %0, {%1, %2};" : "=l"(r) : "f"(lo), "f"(hi));
    return r;
}
__device__ __forceinline__ void fma2(u64& d, u64 a, u64 b) {
    asm("fma.rn.f32x2 %0, %1, %2, %0;" : "+l"(d) : "l"(a), "l"(b));
}

// cp.async helpers
__device__ __forceinline__ void cpa4(uint32_t dst, const void* src, int szbytes) {
    asm volatile("cp.async.ca.shared.global [%0], [%1], 4, %2;"
                 :: "r"(dst), "l"(src), "r"(szbytes));
}
__device__ __forceinline__ void cpa8(uint32_t dst, const void* src) {
    asm volatile("cp.async.ca.shared.global [%0], [%1], 8;"
                 :: "r"(dst), "l"(src));
}
__device__ __forceinline__ void cpa_commit() {
    asm volatile("cp.async.commit_group;" ::: "memory");
}
__device__ __forceinline__ void cpa_wait1() {
    asm volatile("cp.async.wait_group 1;" ::: "memory");
}

// ---------------------------------------------------------------------------
// Phase 2: direct conv, double-buffered cp.async staging, f32x2 math.
// Block = 256 threads, one (n, co), 64x64 output tile, 4x4 outputs/thread.
// ---------------------------------------------------------------------------
__global__ __launch_bounds__(256, 2)
void conv_kernel(const float* __restrict__ x,
                 const float* __restrict__ bias,
                 float* __restrict__ out) {
    __shared__ __align__(16) float tile2[2][TILE_ELEMS];
    __shared__ __align__(16) u64   wsh2[2][9 * WROW];

    const int tid = threadIdx.y * 16 + threadIdx.x;
    const int x0 = blockIdx.x * TILE;
    const int y0 = blockIdx.y * TILE;
    const int n  = blockIdx.z >> 5;
    const int co = blockIdx.z & 31;

    const int ox0 = threadIdx.x * 4;
    const int oy0 = threadIdx.y * 4;

    const float* xn = x + (size_t)n * CIN * HH * WW;
    const u64*   wg = g_w2p + (size_t)co * CIN * 9 * WROW;

    // --- staging lambda (cp.async, zero-fill OOB) ---
    auto stage = [&](int ci, int buf) {
        const float* xc = xn + (size_t)ci * HH * WW;
        uint32_t tb = (uint32_t)__cvta_generic_to_shared(&tile2[buf][0]);
        #pragma unroll
        for (int k = 0; k < 21; k++) {
            int i = tid + k * 256;
            if (i < TILE_ELEMS) {
                int r  = i / SROW;
                int cc = i - r * SROW;
                int gy = y0 - PADV + r;
                int gx = x0 - PADV + cc;
                bool ok = ((unsigned)gy < HH) && ((unsigned)gx < WW);
                const float* src = ok ? &xc[gy * WW + gx] : xc;
                cpa4(tb + i * 4, src, ok ? 4 : 0);
            }
        }
        if (tid < 9 * WROW) {
            uint32_t wb = (uint32_t)__cvta_generic_to_shared(&wsh2[buf][0]);
            cpa8(wb + tid * 8, wg + (size_t)ci * 9 * WROW + tid);
        }
    };

    u64 acc[4][2] = {};

    stage(0, 0);
    cpa_commit();

    for (int ci = 0; ci < CIN; ci++) {
        if (ci + 1 < CIN) stage(ci + 1, (ci + 1) & 1);
        cpa_commit();
        cpa_wait1();            // buffer for ci is complete (this thread's copies)
        __syncthreads();        // make all threads' copies visible

        const int buf = ci & 1;
        const float* tbuf = tile2[buf];
        const u64*   wbase = wsh2[buf];

        #pragma unroll
        for (int r = 0; r < 12; r++) {
            union { float f[12]; u64 a[6]; float4 v[3]; } u;
            const float4* trow = (const float4*)&tbuf[(oy0 + r) * SROW + ox0];
            u.v[0] = trow[0];
            u.v[1] = trow[1];
            u.v[2] = trow[2];
            u64 b[5];
            #pragma unroll
            for (int j = 0; j < 5; j++) b[j] = pk2(u.f[2 * j + 1], u.f[2 * j + 2]);

            #pragma unroll
            for (int oy = 0; oy < 4; oy++) {
                const int ky = r - oy;
                if (ky < 0 || ky > 8) continue;
                const u64* wr = wbase + ky * WROW;
                ulonglong2 w01 = *(const ulonglong2*)(wr + 0);
                ulonglong2 w23 = *(const ulonglong2*)(wr + 2);
                ulonglong2 w45 = *(const ulonglong2*)(wr + 4);
                ulonglong2 w67 = *(const ulonglong2*)(wr + 6);
                u64        w8  = wr[8];

                fma2(acc[oy][0], u.a[0], w01.x); fma2(acc[oy][1], u.a[1], w01.x); // kx=0
                fma2(acc[oy][0], b[0],   w01.y); fma2(acc[oy][1], b[1],   w01.y); // kx=1
                fma2(acc[oy][0], u.a[1], w23.x); fma2(acc[oy][1], u.a[2], w23.x); // kx=2
                fma2(acc[oy][0], b[1],   w23.y); fma2(acc[oy][1], b[2],   w23.y); // kx=3
                fma2(acc[oy][0], u.a[2], w45.x); fma2(acc[oy][1], u.a[3], w45.x); // kx=4
                fma2(acc[oy][0], b[2],   w45.y); fma2(acc[oy][1], b[3],   w45.y); // kx=5
                fma2(acc[oy][0], u.a[3], w67.x); fma2(acc[oy][1], u.a[4], w67.x); // kx=6
                fma2(acc[oy][0], b[3],   w67.y); fma2(acc[oy][1], b[4],   w67.y); // kx=7
                fma2(acc[oy][0], u.a[4], w8);    fma2(acc[oy][1], u.a[5], w8);    // kx=8
            }
        }
        __syncthreads();        // compute on buf done before next stage overwrites it
    }

    const float bv = bias[co];
    float* op = out + (((size_t)(n * COUT + co) * HH + (y0 + oy0)) * WW + x0 + ox0);
    #pragma unroll
    for (int oy = 0; oy < 4; oy++) {
        float o0, o1, o2, o3;
        asm("mov.b64 {%0, %1}, %2;" : "=f"(o0), "=f"(o1) : "l"(acc[oy][0]));
        asm("mov.b64 {%0, %1}, %2;" : "=f"(o2), "=f"(o3) : "l"(acc[oy][1]));
        float4 ov = make_float4(o0 + bv, o1 + bv, o2 + bv, o3 + bv);
        *(float4*)(op + (size_t)oy * WW) = ov;
    }
}

// ---------------------------------------------------------------------------
extern "C" void kernel_launch(void* const* d_in, const int* in_sizes, int n_in,
                              void* d_out, int out_size) {
    const float* x    = (const float*)d_in[0];   // [16, 32, 192, 192]
    const float* wp   = (const float*)d_in[1];   // [32, 32, 3]
    const float* bias = (const float*)d_in[2];   // [32]
    float* out = (float*)d_out;                  // [16, 32, 192, 192]

    gk_compute<<<COUT, CIN>>>(wp);

    dim3 grid(WW / TILE, HH / TILE, NB * COUT);  // (3, 3, 512)
    dim3 blk(16, 16);
    conv_kernel<<<grid, blk>>>(x, bias, out);
}

// round 4
// speedup vs baseline: 1.2315x; 1.0615x over previous
#include <cuda_runtime.h>
#include <cstdint>

#define KS    9
#define PADV  4
#define CIN   32
#define COUT  32
#define HH    192
#define WW    192
#define NB    16
#define CHW   (HH * WW)

#define TILE  64
#define SROW  72                 // 64 + 8 halo
#define TILE_ELEMS (SROW * SROW) // 5184 floats = 1296 16B chunks
#define NCHUNK 1296
#define WROW  10                 // 9 taps padded to 10 u64 (16B alignment)

typedef unsigned long long u64;

// Precomputed Gaussian kernels, duplicated as {w,w} u64 pairs, rows padded to 10.
__device__ u64 g_w2p[COUT * CIN * 9 * WROW];

// ---------------------------------------------------------------------------
// Phase 1: build normalized anisotropic Gaussian kernels from (sx, sy, theta)
// ---------------------------------------------------------------------------
__global__ void gk_compute(const float* __restrict__ wp) {
    int co = blockIdx.x;
    int ci = threadIdx.x;
    const float* p = wp + (co * CIN + ci) * 3;
    float sx = p[0], sy = p[1], th = p[2];
    float rad = th * 0.017453292519943295f;   // th / 180 * pi
    float c = cosf(rad), s = sinf(rad);
    float sx2 = sx * sx, sy2 = sy * sy;
    float a = c * c * sx2 + s * s * sy2;
    float b = c * s * (sx2 - sy2);
    float d = s * s * sx2 + c * c * sy2;
    float det = a * d - b * b;
    float ia = d / det, ib = -b / det, idd = a / det;

    float ker[81];
    float sum = 0.f;
    #pragma unroll
    for (int ky = 0; ky < 9; ky++) {
        float yy = (float)(ky - 4);
        #pragma unroll
        for (int kx = 0; kx < 9; kx++) {
            float xx = (float)(kx - 4);
            float q = ia * xx * xx + 2.0f * ib * xx * yy + idd * yy * yy;
            float v = expf(-0.5f * q);
            ker[ky * 9 + kx] = v;
            sum += v;
        }
    }
    float inv = 1.0f / sum;
    u64* dst = &g_w2p[(co * CIN + ci) * 9 * WROW];
    #pragma unroll
    for (int ky = 0; ky < 9; ky++) {
        #pragma unroll
        for (int kx = 0; kx < 9; kx++) {
            float w = ker[ky * 9 + kx] * inv;
            union { float f[2]; u64 q; } u;
            u.f[0] = w; u.f[1] = w;
            dst[ky * WROW + kx] = u.q;
        }
        dst[ky * WROW + 9] = 0ull;   // pad
    }
}

// ---------------------------------------------------------------------------
// f32x2 / cp.async helpers
// ---------------------------------------------------------------------------
__device__ __forceinline__ u64 pk2(float lo, float hi) {
    u64 r;
    asm("mov.b64 %0, {%1, %2};" : "=l"(r) : "f"(lo), "f"(hi));
    return r;
}
__device__ __forceinline__ void fma2(u64& d, u64 a, u64 b) {
    asm("fma.rn.f32x2 %0, %1, %2, %0;" : "+l"(d) : "l"(a), "l"(b));
}
__device__ __forceinline__ void cpa16(uint32_t dst, const void* src, int szbytes) {
    asm volatile("cp.async.ca.shared.global [%0], [%1], 16, %2;"
                 :: "r"(dst), "l"(src), "r"(szbytes));
}
__device__ __forceinline__ void cpa8(uint32_t dst, const void* src) {
    asm volatile("cp.async.ca.shared.global [%0], [%1], 8;"
                 :: "r"(dst), "l"(src));
}
__device__ __forceinline__ void cpa_commit() {
    asm volatile("cp.async.commit_group;" ::: "memory");
}
__device__ __forceinline__ void cpa_wait1() {
    asm volatile("cp.async.wait_group 1;" ::: "memory");
}
__device__ __forceinline__ void cpa_wait0() {
    asm volatile("cp.async.wait_group 0;" ::: "memory");
}

// ---------------------------------------------------------------------------
// Phase 2: direct conv, double-buffered cp.async staging, f32x2 math.
// Block = 256 threads, one (n, co), 64x64 output tile, 4x4 outputs/thread.
// 3 blocks/SM target (regs <= 84) for latency hiding.
// ---------------------------------------------------------------------------
__global__ __launch_bounds__(256, 3)
void conv_kernel(const float* __restrict__ x,
                 const float* __restrict__ bias,
                 float* __restrict__ out) {
    __shared__ __align__(16) float tile2[2][TILE_ELEMS];
    __shared__ __align__(16) u64   wsh2[2][9 * WROW];

    const int tid = threadIdx.x;
    const int x0 = blockIdx.x * TILE;
    const int y0 = blockIdx.y * TILE;
    const int n  = blockIdx.z >> 5;
    const int co = blockIdx.z & 31;

    const int ox0 = (tid & 15) * 4;
    const int oy0 = (tid >> 4) * 4;

    const float* xn = x + (size_t)n * CIN * CHW;

    // ---- precompute staging pointers: 1296 16B chunks, <=6 per thread ----
    // chunk id -> (row = id/18, col4 = (id%18)*4); OOB is exactly chunk-aligned
    const float* sp[6];
    int szmask = 0;
    #pragma unroll
    for (int k = 0; k < 6; k++) {
        int id = tid + 256 * k;
        sp[k] = xn;
        if (id < NCHUNK) {
            int row = id / 18;
            int c4  = (id - row * 18) * 4;
            int gy  = y0 - PADV + row;
            int gx  = x0 - PADV + c4;
            bool ok = ((unsigned)gy < HH) && ((unsigned)gx <= (WW - 4));
            if (ok) {
                sp[k] = xn + gy * WW + gx;
                szmask |= 1 << k;
            }
        }
    }
    const u64* wpp = g_w2p + (size_t)co * CIN * 9 * WROW + tid;

    const uint32_t tb0 = (uint32_t)__cvta_generic_to_shared(&tile2[0][0]) + tid * 16;
    const uint32_t tb1 = (uint32_t)__cvta_generic_to_shared(&tile2[1][0]) + tid * 16;
    const uint32_t wb0 = (uint32_t)__cvta_generic_to_shared(&wsh2[0][0]) + tid * 8;
    const uint32_t wb1 = (uint32_t)__cvta_generic_to_shared(&wsh2[1][0]) + tid * 8;

    // stage channel data into buffer buf, then advance pointers by one channel
    auto stage = [&](int buf) {
        uint32_t tb = buf ? tb1 : tb0;
        #pragma unroll
        for (int k = 0; k < 6; k++) {
            if (k < 5 || tid < NCHUNK - 5 * 256) {
                cpa16(tb + k * 4096, sp[k], ((szmask >> k) & 1) << 4);
                sp[k] += CHW;
            }
        }
        if (tid < 9 * WROW) {
            cpa8(buf ? wb1 : wb0, wpp);
        }
        wpp += 9 * WROW;
    };

    u64 acc[4][2] = {};

    stage(0);
    cpa_commit();

    for (int ci = 0; ci < CIN; ci++) {
        if (ci + 1 < CIN) {
            stage((ci + 1) & 1);
            cpa_commit();
            cpa_wait1();        // stage(ci) fully issued->landed
        } else {
            cpa_wait0();
        }
        __syncthreads();        // all threads' copies visible

        const int buf = ci & 1;
        const float* tbuf = tile2[buf];
        const u64*   wbase = wsh2[buf];

        #pragma unroll
        for (int r = 0; r < 12; r++) {
            union { float f[12]; u64 a[6]; float4 v[3]; } u;
            const float4* trow = (const float4*)&tbuf[(oy0 + r) * SROW + ox0];
            u.v[0] = trow[0];
            u.v[1] = trow[1];
            u.v[2] = trow[2];
            u64 b[5];
            #pragma unroll
            for (int j = 0; j < 5; j++) b[j] = pk2(u.f[2 * j + 1], u.f[2 * j + 2]);

            #pragma unroll
            for (int oy = 0; oy < 4; oy++) {
                const int ky = r - oy;
                if (ky < 0 || ky > 8) continue;
                const u64* wr = wbase + ky * WROW;
                ulonglong2 w01 = *(const ulonglong2*)(wr + 0);
                ulonglong2 w23 = *(const ulonglong2*)(wr + 2);
                ulonglong2 w45 = *(const ulonglong2*)(wr + 4);
                ulonglong2 w67 = *(const ulonglong2*)(wr + 6);
                u64        w8  = wr[8];

                fma2(acc[oy][0], u.a[0], w01.x); fma2(acc[oy][1], u.a[1], w01.x); // kx=0
                fma2(acc[oy][0], b[0],   w01.y); fma2(acc[oy][1], b[1],   w01.y); // kx=1
                fma2(acc[oy][0], u.a[1], w23.x); fma2(acc[oy][1], u.a[2], w23.x); // kx=2
                fma2(acc[oy][0], b[1],   w23.y); fma2(acc[oy][1], b[2],   w23.y); // kx=3
                fma2(acc[oy][0], u.a[2], w45.x); fma2(acc[oy][1], u.a[3], w45.x); // kx=4
                fma2(acc[oy][0], b[2],   w45.y); fma2(acc[oy][1], b[3],   w45.y); // kx=5
                fma2(acc[oy][0], u.a[3], w67.x); fma2(acc[oy][1], u.a[4], w67.x); // kx=6
                fma2(acc[oy][0], b[3],   w67.y); fma2(acc[oy][1], b[4],   w67.y); // kx=7
                fma2(acc[oy][0], u.a[4], w8);    fma2(acc[oy][1], u.a[5], w8);    // kx=8
            }
        }
        __syncthreads();        // compute on buf done before it is re-staged
    }

    const float bv = bias[co];
    float* op = out + (((size_t)(n * COUT + co) * HH + (y0 + oy0)) * WW + x0 + ox0);
    #pragma unroll
    for (int oy = 0; oy < 4; oy++) {
        float o0, o1, o2, o3;
        asm("mov.b64 {%0, %1}, %2;" : "=f"(o0), "=f"(o1) : "l"(acc[oy][0]));
        asm("mov.b64 {%0, %1}, %2;" : "=f"(o2), "=f"(o3) : "l"(acc[oy][1]));
        float4 ov = make_float4(o0 + bv, o1 + bv, o2 + bv, o3 + bv);
        *(float4*)(op + (size_t)oy * WW) = ov;
    }
}

// ---------------------------------------------------------------------------
extern "C" void kernel_launch(void* const* d_in, const int* in_sizes, int n_in,
                              void* d_out, int out_size) {
    const float* x    = (const float*)d_in[0];   // [16, 32, 192, 192]
    const float* wp   = (const float*)d_in[1];   // [32, 32, 3]
    const float* bias = (const float*)d_in[2];   // [32]
    float* out = (float*)d_out;                  // [16, 32, 192, 192]

    gk_compute<<<COUT, CIN>>>(wp);

    dim3 grid(WW / TILE, HH / TILE, NB * COUT);  // (3, 3, 512)
    dim3 blk(256);
    conv_kernel<<<grid, blk>>>(x, bias, out);
}